// round 3
// baseline (speedup 1.0000x reference)
#include <cuda_runtime.h>
#include <cstdint>

#define B_ 256
#define H_ 1024
#define D_ 256
#define C_ 16
#define G_ 32
#define O_ 256
#define HD_ 1280  // H + D

// Scratch (no cudaMalloc allowed): ~19 MB of __device__ globals.
__device__ float g_ebias[C_ * G_ * H_];    // [c][g][h]  enc_part + attn_b
__device__ float g_hid[B_ * C_ * H_];      // [b][c][h]  hid_part
__device__ float g_scores[B_ * C_ * G_];   // [b][c][g]
__device__ float g_pooled[B_ * D_];        // [b][d]

// ---------------- packed fp32x2 helpers (Blackwell dual-FMA) ----------------
__device__ __forceinline__ unsigned long long pack2(float x, float y) {
    unsigned long long r;
    asm("mov.b64 %0, {%1, %2};" : "=l"(r) : "f"(x), "f"(y));
    return r;
}
__device__ __forceinline__ void unpack2(unsigned long long p, float& x, float& y) {
    asm("mov.b64 {%0, %1}, %2;" : "=f"(x), "=f"(y) : "l"(p));
}
__device__ __forceinline__ unsigned long long ffma2(unsigned long long a,
                                                    unsigned long long b,
                                                    unsigned long long c) {
    unsigned long long d;
    asm("fma.rn.f32x2 %0, %1, %2, %3;" : "=l"(d) : "l"(a), "l"(b), "l"(c));
    return d;
}

// Accurate-enough tanh: 2 MUFU, ~1e-7 abs error, correct saturation.
// tanh(x) = 1 - 2/(1 + exp2(2*log2(e)*x))
__device__ __forceinline__ float tanh_fast(float x) {
    float e, r;
    asm("ex2.approx.f32 %0, %1;" : "=f"(e) : "f"(x * 2.8853900817779268f));
    asm("rcp.approx.f32 %0, %1;" : "=f"(r) : "f"(e + 1.0f));
    return fmaf(-2.0f, r, 1.0f);
}

// ---------------- K1: ebias[c][g][o] = sum_d gst[c][g][d]*w_enc[c][o][d] + b[c][o]
__global__ void __launch_bounds__(256) ebias_kernel(
    const float* __restrict__ gst_emb, const float* __restrict__ attn_w,
    const float* __restrict__ attn_b)
{
    int c = blockIdx.x;
    int o = blockIdx.y * 128 + (threadIdx.x & 127);
    int gbase = (threadIdx.x >> 7) * 16;
    __shared__ float gs[G_][D_];
    const float4* src = (const float4*)(gst_emb + (size_t)c * G_ * D_);
    for (int i = threadIdx.x; i < G_ * D_ / 4; i += 256)
        ((float4*)gs)[i] = src[i];
    __syncthreads();

    float acc[16];
    #pragma unroll
    for (int g = 0; g < 16; g++) acc[g] = 0.f;

    const float* wrow = attn_w + (size_t)c * H_ * HD_ + (size_t)o * HD_ + H_;
    for (int d = 0; d < D_; d += 4) {
        float4 w4 = *(const float4*)(wrow + d);
        #pragma unroll
        for (int g = 0; g < 16; g++) {
            float a = acc[g];
            a = fmaf(gs[gbase + g][d],     w4.x, a);
            a = fmaf(gs[gbase + g][d + 1], w4.y, a);
            a = fmaf(gs[gbase + g][d + 2], w4.z, a);
            a = fmaf(gs[gbase + g][d + 3], w4.w, a);
            acc[g] = a;
        }
    }
    float bias = attn_b[c * H_ + o];
    #pragma unroll
    for (int g = 0; g < 16; g++)
        g_ebias[(size_t)c * G_ * H_ + (size_t)(gbase + g) * H_ + o] = acc[g] + bias;
}

// ---------------- K2: hid_part GEMM, fp32 via packed f32x2 FMAs ----------------
// Per c: C(256x1024) = hidden(256x1024) * W^T, W = attn_w[c][:, :1024] (N=1024,K=1024)
#define BM 128
#define BN 128
#define BK 16
#define LDA 132   // 132 floats = 528 B, multiple of 16 B -> float4/u64x2 smem loads stay aligned

__global__ void __launch_bounds__(256) hid_gemm_kernel(
    const float* __restrict__ hidden, const float* __restrict__ attn_w)
{
    int c = blockIdx.z;
    int bn0 = blockIdx.x * BN;
    int bm0 = blockIdx.y * BM;
    __shared__ float As[2][BK][LDA];
    __shared__ float Bs[2][BK][LDA];
    int t = threadIdx.x;
    int lrow = t >> 2;          // 0..63
    int lkv  = (t & 3) * 4;     // 0,4,8,12
    int tx = t & 15, ty = t >> 4;

    const float* Abase = hidden + (size_t)bm0 * H_;
    const float* Bbase = attn_w + (size_t)c * H_ * HD_ + (size_t)bn0 * HD_;

    unsigned long long acc[8][4];
    #pragma unroll
    for (int i = 0; i < 8; i++)
        #pragma unroll
        for (int j = 0; j < 4; j++) acc[i][j] = 0ULL;

    float4 ra[2], rb[2];
    #pragma unroll
    for (int p = 0; p < 2; p++) {
        int r = p * 64 + lrow;
        ra[p] = *(const float4*)(Abase + (size_t)r * H_  + lkv);
        rb[p] = *(const float4*)(Bbase + (size_t)r * HD_ + lkv);
    }
    #pragma unroll
    for (int p = 0; p < 2; p++) {
        int r = p * 64 + lrow;
        As[0][lkv+0][r] = ra[p].x; As[0][lkv+1][r] = ra[p].y;
        As[0][lkv+2][r] = ra[p].z; As[0][lkv+3][r] = ra[p].w;
        Bs[0][lkv+0][r] = rb[p].x; Bs[0][lkv+1][r] = rb[p].y;
        Bs[0][lkv+2][r] = rb[p].z; Bs[0][lkv+3][r] = rb[p].w;
    }
    __syncthreads();

    const int NK = H_ / BK;  // 64
    for (int kt = 0; kt < NK; kt++) {
        int cur = kt & 1;
        if (kt + 1 < NK) {
            int k0 = (kt + 1) * BK;
            #pragma unroll
            for (int p = 0; p < 2; p++) {
                int r = p * 64 + lrow;
                ra[p] = *(const float4*)(Abase + (size_t)r * H_  + k0 + lkv);
                rb[p] = *(const float4*)(Bbase + (size_t)r * HD_ + k0 + lkv);
            }
        }
        #pragma unroll
        for (int kk = 0; kk < BK; kk++) {
            float4 a0 = *(const float4*)&As[cur][kk][ty * 4];
            float4 a1 = *(const float4*)&As[cur][kk][64 + ty * 4];
            // b pairs come straight out of smem as u64 — no pack cost
            ulonglong2 b01 = *(const ulonglong2*)&Bs[cur][kk][tx * 4];
            ulonglong2 b23 = *(const ulonglong2*)&Bs[cur][kk][64 + tx * 4];
            float am[8] = {a0.x, a0.y, a0.z, a0.w, a1.x, a1.y, a1.z, a1.w};
            #pragma unroll
            for (int i = 0; i < 8; i++) {
                unsigned long long ad = pack2(am[i], am[i]);
                acc[i][0] = ffma2(ad, b01.x, acc[i][0]);
                acc[i][1] = ffma2(ad, b01.y, acc[i][1]);
                acc[i][2] = ffma2(ad, b23.x, acc[i][2]);
                acc[i][3] = ffma2(ad, b23.y, acc[i][3]);
            }
        }
        if (kt + 1 < NK) {
            __syncthreads();
            int nxt = cur ^ 1;
            #pragma unroll
            for (int p = 0; p < 2; p++) {
                int r = p * 64 + lrow;
                As[nxt][lkv+0][r] = ra[p].x; As[nxt][lkv+1][r] = ra[p].y;
                As[nxt][lkv+2][r] = ra[p].z; As[nxt][lkv+3][r] = ra[p].w;
                Bs[nxt][lkv+0][r] = rb[p].x; Bs[nxt][lkv+1][r] = rb[p].y;
                Bs[nxt][lkv+2][r] = rb[p].z; Bs[nxt][lkv+3][r] = rb[p].w;
            }
            __syncthreads();
        }
    }

    // epilogue -> g_hid[b][c][o]
    #pragma unroll
    for (int i = 0; i < 8; i++) {
        int m = (i < 4) ? (ty * 4 + i) : (64 + ty * 4 + i - 4);
        float* dst = g_hid + (size_t)(bm0 + m) * (C_ * H_) + (size_t)c * H_ + bn0;
        float x0, x1, x2, x3;
        unpack2(acc[i][0], x0, x1);
        unpack2(acc[i][1], x2, x3);
        *(float4*)(dst + tx * 4) = make_float4(x0, x1, x2, x3);
        unpack2(acc[i][2], x0, x1);
        unpack2(acc[i][3], x2, x3);
        *(float4*)(dst + 64 + tx * 4) = make_float4(x0, x1, x2, x3);
    }
}

// ---------------- K3: scores[b][c][g] = sum_h v[c][h]*tanh(hid + ebias) ----------------
__global__ void __launch_bounds__(256) scores_kernel(const float* __restrict__ v)
{
    int c = blockIdx.x;
    int b0 = blockIdx.y * 16;
    __shared__ float hidS[16][65];  // stride 65: lanes b0..15 -> distinct banks
    __shared__ float ebS[32][65];
    __shared__ float vS[64];
    int t = threadIdx.x;
    int bb = t & 15;
    int q  = t >> 4;   // g pair {q, q+16}
    float acc0 = 0.f, acc1 = 0.f;

    for (int hc = 0; hc < H_; hc += 64) {
        {
            int i = t >> 4, j4 = (t & 15) * 4;
            float4 hv = *(const float4*)(g_hid + (size_t)(b0 + i) * (C_ * H_) + (size_t)c * H_ + hc + j4);
            hidS[i][j4] = hv.x; hidS[i][j4+1] = hv.y; hidS[i][j4+2] = hv.z; hidS[i][j4+3] = hv.w;
        }
        #pragma unroll
        for (int p = 0; p < 2; p++) {
            int idx = t + p * 256;
            int g = idx >> 4, j4 = (idx & 15) * 4;
            float4 ev = *(const float4*)(g_ebias + (size_t)c * (G_ * H_) + (size_t)g * H_ + hc + j4);
            ebS[g][j4] = ev.x; ebS[g][j4+1] = ev.y; ebS[g][j4+2] = ev.z; ebS[g][j4+3] = ev.w;
        }
        if (t < 16) {
            float4 vv = *(const float4*)(v + (size_t)c * H_ + hc + t * 4);
            vS[t*4] = vv.x; vS[t*4+1] = vv.y; vS[t*4+2] = vv.z; vS[t*4+3] = vv.w;
        }
        __syncthreads();
        #pragma unroll 8
        for (int j = 0; j < 64; j++) {
            float x  = hidS[bb][j];
            float vv = vS[j];
            acc0 = fmaf(vv, tanh_fast(x + ebS[q][j]),      acc0);
            acc1 = fmaf(vv, tanh_fast(x + ebS[q + 16][j]), acc1);
        }
        __syncthreads();
    }
    g_scores[(size_t)(b0 + bb) * (C_ * G_) + c * G_ + q]      = acc0;
    g_scores[(size_t)(b0 + bb) * (C_ * G_) + c * G_ + q + 16] = acc1;
}

// ---------------- K4a: softmax over g, write att_cat ----------------
__global__ void __launch_bounds__(512) softmax_kernel(float* __restrict__ att)
{
    int b = blockIdx.x;
    int c = threadIdx.x >> 5;
    int g = threadIdx.x & 31;
    float s = g_scores[(size_t)b * (C_ * G_) + c * G_ + g];
    float m = s;
    #pragma unroll
    for (int off = 16; off > 0; off >>= 1)
        m = fmaxf(m, __shfl_xor_sync(0xffffffffu, m, off));
    float e = __expf(s - m);
    float sum = e;
    #pragma unroll
    for (int off = 16; off > 0; off >>= 1)
        sum += __shfl_xor_sync(0xffffffffu, sum, off);
    att[(size_t)b * (C_ * G_) + c * G_ + g] = e / sum;
}

// ---------------- K4b: pooled[b][d] = (1/C) * sum_cg att[b][cg]*emb[cg][d] ----------------
__global__ void __launch_bounds__(256) pooled_kernel(
    const float* __restrict__ att, const float* __restrict__ gst_emb)
{
    int b0 = blockIdx.x * 8;
    int d = threadIdx.x;
    __shared__ float attS[8][C_ * G_];
    #pragma unroll
    for (int p = 0; p < 16; p++) {
        int idx = threadIdx.x + p * 256;
        attS[idx >> 9][idx & 511] = att[(size_t)b0 * 512 + idx];
    }
    __syncthreads();
    float acc[8];
    #pragma unroll
    for (int i = 0; i < 8; i++) acc[i] = 0.f;
    for (int cg = 0; cg < C_ * G_; cg++) {
        float e = gst_emb[(size_t)cg * D_ + d];
        #pragma unroll
        for (int i = 0; i < 8; i++) acc[i] = fmaf(attS[i][cg], e, acc[i]);
    }
    #pragma unroll
    for (int i = 0; i < 8; i++)
        g_pooled[(size_t)(b0 + i) * D_ + d] = acc[i] * (1.0f / C_);
}

// ---------------- K4c: out[b][o] = pooled[b] . out_w[o] + out_b[o] ----------------
__global__ void __launch_bounds__(256) out_kernel(
    const float* __restrict__ out_w, const float* __restrict__ out_b,
    float* __restrict__ outp)
{
    int b0 = blockIdx.x * 8;
    int o = threadIdx.x;
    __shared__ float ps[8][D_];
    #pragma unroll
    for (int p = 0; p < 8; p++) {
        int idx = threadIdx.x + p * 256;
        ps[idx >> 8][idx & 255] = g_pooled[(size_t)b0 * D_ + idx];
    }
    __syncthreads();
    float acc[8];
    #pragma unroll
    for (int i = 0; i < 8; i++) acc[i] = 0.f;
    const float* wrow = out_w + (size_t)o * D_;
    for (int dd = 0; dd < D_; dd += 4) {
        float4 w4 = *(const float4*)(wrow + dd);
        #pragma unroll
        for (int i = 0; i < 8; i++) {
            float a = acc[i];
            a = fmaf(ps[i][dd],     w4.x, a);
            a = fmaf(ps[i][dd + 1], w4.y, a);
            a = fmaf(ps[i][dd + 2], w4.z, a);
            a = fmaf(ps[i][dd + 3], w4.w, a);
            acc[i] = a;
        }
    }
    float bias = out_b[o];
    #pragma unroll
    for (int i = 0; i < 8; i++)
        outp[(size_t)(b0 + i) * O_ + o] = acc[i] + bias;
}

extern "C" void kernel_launch(void* const* d_in, const int* in_sizes, int n_in,
                              void* d_out, int out_size)
{
    const float* hidden  = (const float*)d_in[0];
    const float* gst_emb = (const float*)d_in[1];
    const float* attn_w  = (const float*)d_in[2];
    const float* attn_b  = (const float*)d_in[3];
    const float* v       = (const float*)d_in[4];
    const float* out_w   = (const float*)d_in[5];
    const float* out_b   = (const float*)d_in[6];
    float* out = (float*)d_out;
    float* att  = out;                   // [B, C*G] = 131072 floats
    float* outp = out + B_ * C_ * G_;    // [B, O]   = 65536 floats

    ebias_kernel  <<<dim3(C_, 8),      256>>>(gst_emb, attn_w, attn_b);
    hid_gemm_kernel<<<dim3(8, 2, C_),  256>>>(hidden, attn_w);
    scores_kernel <<<dim3(C_, 16),     256>>>(v);
    softmax_kernel<<<B_,               512>>>(att);
    pooled_kernel <<<B_ / 8,           256>>>(att, gst_emb);
    out_kernel    <<<B_ / 8,           256>>>(out_w, out_b, outp);
}

// round 5
// speedup vs baseline: 1.2134x; 1.2134x over previous
#include <cuda_runtime.h>
#include <cuda_bf16.h>
#include <cstdint>

#define B_ 256
#define H_ 1024
#define D_ 256
#define C_ 16
#define G_ 32
#define O_ 256
#define HD_ 1280  // H + D

// ---------------- device-global scratch (no cudaMalloc allowed) ----------------
__device__ float g_ebias[C_ * G_ * H_];    // [c][g][h]
__device__ float g_hid[B_ * C_ * H_];      // [b][c][h]
__device__ float g_scores[B_ * C_ * G_];   // [b][c][g]
__device__ float g_pooled[B_ * D_];        // [b][d]

// bf16 hi/lo split operands, plain row-major (k contiguous).
__device__ uint4 g_ah[B_ * H_ / 8];            // A hi  [m][k]   0.5 MB
__device__ uint4 g_al[B_ * H_ / 8];            // A lo
__device__ uint4 g_wh[C_ * H_ * H_ / 8];       // W hi  [c][n][k]  32 MB
__device__ uint4 g_wl[C_ * H_ * H_ / 8];       // W lo

// ---------------- helpers ----------------
__device__ __forceinline__ uint32_t smem_u32(const void* p) {
    uint32_t a;
    asm("{ .reg .u64 t; cvta.to.shared.u64 t, %1; cvt.u32.u64 %0, t; }"
        : "=r"(a) : "l"(p));
    return a;
}
__device__ __forceinline__ void cp16(uint32_t dst, const void* src) {
    asm volatile("cp.async.cg.shared.global [%0], [%1], 16;"
                 :: "r"(dst), "l"(src) : "memory");
}
__device__ __forceinline__ void ldsm4(uint32_t* r, uint32_t addr) {
    asm volatile("ldmatrix.sync.aligned.m8n8.x4.shared.b16 {%0,%1,%2,%3}, [%4];"
                 : "=r"(r[0]), "=r"(r[1]), "=r"(r[2]), "=r"(r[3]) : "r"(addr));
}
__device__ __forceinline__ void mma16816(float* d, const uint32_t* a, const uint32_t* b) {
    asm volatile(
        "mma.sync.aligned.m16n8k16.row.col.f32.bf16.bf16.f32 "
        "{%0,%1,%2,%3}, {%4,%5,%6,%7}, {%8,%9}, {%0,%1,%2,%3};"
        : "+f"(d[0]), "+f"(d[1]), "+f"(d[2]), "+f"(d[3])
        : "r"(a[0]), "r"(a[1]), "r"(a[2]), "r"(a[3]), "r"(b[0]), "r"(b[1]));
}
// Accurate tanh: 2 MUFU, ~1e-7 abs error, correct saturation.
__device__ __forceinline__ float tanh_fast(float x) {
    float e, r;
    asm("ex2.approx.f32 %0, %1;" : "=f"(e) : "f"(x * 2.8853900817779268f));
    asm("rcp.approx.f32 %0, %1;" : "=f"(r) : "f"(e + 1.0f));
    return fmaf(-2.0f, r, 1.0f);
}
__device__ __forceinline__ void split8(const float* xs, uint32_t* hw, uint32_t* lw) {
    #pragma unroll
    for (int i = 0; i < 4; i++) {
        __nv_bfloat16 h0 = __float2bfloat16(xs[2*i]);
        __nv_bfloat16 h1 = __float2bfloat16(xs[2*i+1]);
        __nv_bfloat16 l0 = __float2bfloat16(xs[2*i]   - __bfloat162float(h0));
        __nv_bfloat16 l1 = __float2bfloat16(xs[2*i+1] - __bfloat162float(h1));
        hw[i] = (uint32_t)__bfloat16_as_ushort(h0) | ((uint32_t)__bfloat16_as_ushort(h1) << 16);
        lw[i] = (uint32_t)__bfloat16_as_ushort(l0) | ((uint32_t)__bfloat16_as_ushort(l1) << 16);
    }
}

// ---------------- K0a: split hidden -> bf16 hi/lo ----------------
__global__ void __launch_bounds__(256) convert_a_kernel(const float* __restrict__ hidden)
{
    int idx = blockIdx.x * 256 + threadIdx.x;   // 32768
    int b = idx >> 7, j = idx & 127;
    const float4* s = (const float4*)(hidden + (size_t)b * H_ + j * 8);
    float4 x0 = s[0], x1 = s[1];
    float xs[8] = {x0.x, x0.y, x0.z, x0.w, x1.x, x1.y, x1.z, x1.w};
    uint32_t hw[4], lw[4];
    split8(xs, hw, lw);
    g_ah[b * 128 + j] = make_uint4(hw[0], hw[1], hw[2], hw[3]);
    g_al[b * 128 + j] = make_uint4(lw[0], lw[1], lw[2], lw[3]);
}

// ---------------- K0b: split w_hid -> bf16 hi/lo ----------------
__global__ void __launch_bounds__(256) convert_w_kernel(const float* __restrict__ attn_w)
{
    int idx = blockIdx.x * 256 + threadIdx.x;   // 2,097,152
    int j = idx & 127;
    int o = (idx >> 7) & 1023;
    int c = idx >> 17;
    const float4* s = (const float4*)(attn_w + ((size_t)c * H_ + o) * HD_ + j * 8);
    float4 x0 = s[0], x1 = s[1];
    float xs[8] = {x0.x, x0.y, x0.z, x0.w, x1.x, x1.y, x1.z, x1.w};
    uint32_t hw[4], lw[4];
    split8(xs, hw, lw);
    size_t u = (size_t)c * 131072 + (size_t)o * 128 + j;
    g_wh[u] = make_uint4(hw[0], hw[1], hw[2], hw[3]);
    g_wl[u] = make_uint4(lw[0], lw[1], lw[2], lw[3]);
}

// ---------------- K1: ebias ----------------
__global__ void __launch_bounds__(256) ebias_kernel(
    const float* __restrict__ gst_emb, const float* __restrict__ attn_w,
    const float* __restrict__ attn_b)
{
    int c = blockIdx.x;
    int o = blockIdx.y * 128 + (threadIdx.x & 127);
    int gbase = (threadIdx.x >> 7) * 16;
    __shared__ float gs[G_][D_];
    const float4* src = (const float4*)(gst_emb + (size_t)c * G_ * D_);
    for (int i = threadIdx.x; i < G_ * D_ / 4; i += 256)
        ((float4*)gs)[i] = src[i];
    __syncthreads();

    float acc[16];
    #pragma unroll
    for (int g = 0; g < 16; g++) acc[g] = 0.f;

    const float* wrow = attn_w + (size_t)c * H_ * HD_ + (size_t)o * HD_ + H_;
    for (int d = 0; d < D_; d += 4) {
        float4 w4 = *(const float4*)(wrow + d);
        #pragma unroll
        for (int g = 0; g < 16; g++) {
            float a = acc[g];
            a = fmaf(gs[gbase + g][d],     w4.x, a);
            a = fmaf(gs[gbase + g][d + 1], w4.y, a);
            a = fmaf(gs[gbase + g][d + 2], w4.z, a);
            a = fmaf(gs[gbase + g][d + 3], w4.w, a);
            acc[g] = a;
        }
    }
    float bias = attn_b[c * H_ + o];
    #pragma unroll
    for (int g = 0; g < 16; g++)
        g_ebias[(size_t)c * G_ * H_ + (size_t)(gbase + g) * H_ + o] = acc[g] + bias;
}

// ---------------- K2: hid_part GEMM via mma.sync bf16 hi/lo ----------------
// grid (8, 2, 16): BN=128, BM=128, per c. 8 warps: wm in {0,1} (64 rows), wn in 0..3 (32 cols).
#define LDROW 80                    // smem row stride bytes (32 bf16 + 16B pad)
#define TILEB (128 * LDROW)         // 10240
#define STAGEB (4 * TILEB)          // Ah, Al, Bh, Bl
#define GSMEM (2 * STAGEB)          // 81920
#define NKC 32                      // K / 32

__global__ void __launch_bounds__(256) gemm_mma_kernel()
{
    extern __shared__ char smem[];
    uint32_t sb = smem_u32(smem);
    int t = threadIdx.x, w = t >> 5, l = t & 31;
    int wm = w & 1, wn = w >> 1;
    int bn0 = blockIdx.x * 128, bm0 = blockIdx.y * 128, c = blockIdx.z;

    const uint4* pAh = g_ah + (size_t)bm0 * 128;
    const uint4* pAl = g_al + (size_t)bm0 * 128;
    const uint4* pBh = g_wh + (size_t)c * 131072 + (size_t)bn0 * 128;
    const uint4* pBl = g_wl + (size_t)c * 131072 + (size_t)bn0 * 128;

    int row = t >> 2, q = t & 3;          // copy indexing: 2 rows per thread group
    uint32_t cpdst = (uint32_t)(row * LDROW + q * 16);

    float acc[4][4][4];
    #pragma unroll
    for (int i = 0; i < 4; i++)
        #pragma unroll
        for (int j = 0; j < 4; j++)
            #pragma unroll
            for (int k = 0; k < 4; k++) acc[i][j][k] = 0.f;

    // async-copy one stage (kc-th 32-wide K chunk)
    auto stage_load = [&](int kc, int buf) {
        uint32_t base = sb + buf * STAGEB;
        #pragma unroll
        for (int h = 0; h < 2; h++) {
            int r = row + h * 64;
            int su = r * 128 + kc * 4 + q;
            uint32_t d = base + cpdst + h * 64 * LDROW;
            cp16(d,              pAh + su);
            cp16(d + TILEB,      pAl + su);
            cp16(d + 2 * TILEB,  pBh + su);
            cp16(d + 3 * TILEB,  pBl + su);
        }
        asm volatile("cp.async.commit_group;" ::: "memory");
    };

    stage_load(0, 0);

    uint32_t arow_off = (uint32_t)((l & 15) * LDROW + (l >> 4) * 16);
    uint32_t brow_off = (uint32_t)((((l & 7) + ((l >> 4) << 3)) * LDROW) + ((l >> 3) & 1) * 16);

    for (int kc = 0; kc < NKC; kc++) {
        int cur = kc & 1;
        if (kc + 1 < NKC) {
            stage_load(kc + 1, cur ^ 1);
            asm volatile("cp.async.wait_group 1;" ::: "memory");
        } else {
            asm volatile("cp.async.wait_group 0;" ::: "memory");
        }
        __syncthreads();

        uint32_t base = sb + cur * STAGEB;
        #pragma unroll
        for (int kk = 0; kk < 2; kk++) {
            uint32_t kkb = kk * 32;
            uint32_t aH[4][4], aL[4][4], bH[2][4], bL[2][4];
            #pragma unroll
            for (int mt = 0; mt < 4; mt++) {
                uint32_t ad = base + (uint32_t)((wm * 64 + mt * 16) * LDROW) + kkb + arow_off;
                ldsm4(aH[mt], ad);
                ldsm4(aL[mt], ad + TILEB);
            }
            #pragma unroll
            for (int p = 0; p < 2; p++) {
                uint32_t bd = base + 2 * TILEB +
                              (uint32_t)((wn * 32 + p * 16) * LDROW) + kkb + brow_off;
                ldsm4(bH[p], bd);
                ldsm4(bL[p], bd + TILEB);
            }
            #pragma unroll
            for (int mt = 0; mt < 4; mt++)
                #pragma unroll
                for (int p = 0; p < 2; p++)
                    #pragma unroll
                    for (int hf = 0; hf < 2; hf++) {
                        int nt = p * 2 + hf;
                        mma16816(acc[mt][nt], aH[mt], &bH[p][hf * 2]);
                        mma16816(acc[mt][nt], aH[mt], &bL[p][hf * 2]);
                        mma16816(acc[mt][nt], aL[mt], &bH[p][hf * 2]);
                    }
        }
        __syncthreads();
    }

    // epilogue -> g_hid[b][c][h]
    #pragma unroll
    for (int mt = 0; mt < 4; mt++) {
        int m0 = bm0 + wm * 64 + mt * 16 + (l >> 2);
        #pragma unroll
        for (int nt = 0; nt < 4; nt++) {
            int col = bn0 + wn * 32 + nt * 8 + (l & 3) * 2;
            float* d0 = g_hid + (size_t)m0 * (C_ * H_) + (size_t)c * H_ + col;
            *(float2*)d0 = make_float2(acc[mt][nt][0], acc[mt][nt][1]);
            *(float2*)(d0 + (size_t)8 * C_ * H_) = make_float2(acc[mt][nt][2], acc[mt][nt][3]);
        }
    }
}

// ---------------- K3: scores ----------------
__global__ void __launch_bounds__(256) scores_kernel(const float* __restrict__ v)
{
    int c = blockIdx.x;
    int b0 = blockIdx.y * 16;
    __shared__ float hidS[16][65];
    __shared__ float ebS[32][65];
    __shared__ float vS[64];
    int t = threadIdx.x;
    int bb = t & 15;
    int q  = t >> 4;
    float acc0 = 0.f, acc1 = 0.f;

    for (int hc = 0; hc < H_; hc += 64) {
        {
            int i = t >> 4, j4 = (t & 15) * 4;
            float4 hv = *(const float4*)(g_hid + (size_t)(b0 + i) * (C_ * H_) + (size_t)c * H_ + hc + j4);
            hidS[i][j4] = hv.x; hidS[i][j4+1] = hv.y; hidS[i][j4+2] = hv.z; hidS[i][j4+3] = hv.w;
        }
        #pragma unroll
        for (int p = 0; p < 2; p++) {
            int idx = t + p * 256;
            int g = idx >> 4, j4 = (idx & 15) * 4;
            float4 ev = *(const float4*)(g_ebias + (size_t)c * (G_ * H_) + (size_t)g * H_ + hc + j4);
            ebS[g][j4] = ev.x; ebS[g][j4+1] = ev.y; ebS[g][j4+2] = ev.z; ebS[g][j4+3] = ev.w;
        }
        if (t < 16) {
            float4 vv = *(const float4*)(v + (size_t)c * H_ + hc + t * 4);
            vS[t*4] = vv.x; vS[t*4+1] = vv.y; vS[t*4+2] = vv.z; vS[t*4+3] = vv.w;
        }
        __syncthreads();
        #pragma unroll 8
        for (int j = 0; j < 64; j++) {
            float x  = hidS[bb][j];
            float vv = vS[j];
            acc0 = fmaf(vv, tanh_fast(x + ebS[q][j]),      acc0);
            acc1 = fmaf(vv, tanh_fast(x + ebS[q + 16][j]), acc1);
        }
        __syncthreads();
    }
    g_scores[(size_t)(b0 + bb) * (C_ * G_) + c * G_ + q]      = acc0;
    g_scores[(size_t)(b0 + bb) * (C_ * G_) + c * G_ + q + 16] = acc1;
}

// ---------------- K4a: softmax ----------------
__global__ void __launch_bounds__(512) softmax_kernel(float* __restrict__ att)
{
    int b = blockIdx.x;
    int c = threadIdx.x >> 5;
    int g = threadIdx.x & 31;
    float s = g_scores[(size_t)b * (C_ * G_) + c * G_ + g];
    float m = s;
    #pragma unroll
    for (int off = 16; off > 0; off >>= 1)
        m = fmaxf(m, __shfl_xor_sync(0xffffffffu, m, off));
    float e = __expf(s - m);
    float sum = e;
    #pragma unroll
    for (int off = 16; off > 0; off >>= 1)
        sum += __shfl_xor_sync(0xffffffffu, sum, off);
    att[(size_t)b * (C_ * G_) + c * G_ + g] = e / sum;
}

// ---------------- K4b: pooled ----------------
__global__ void __launch_bounds__(256) pooled_kernel(
    const float* __restrict__ att, const float* __restrict__ gst_emb)
{
    int b0 = blockIdx.x * 8;
    int d = threadIdx.x;
    __shared__ float attS[8][C_ * G_];
    #pragma unroll
    for (int p = 0; p < 16; p++) {
        int idx = threadIdx.x + p * 256;
        attS[idx >> 9][idx & 511] = att[(size_t)b0 * 512 + idx];
    }
    __syncthreads();
    float acc[8];
    #pragma unroll
    for (int i = 0; i < 8; i++) acc[i] = 0.f;
    for (int cg = 0; cg < C_ * G_; cg++) {
        float e = gst_emb[(size_t)cg * D_ + d];
        #pragma unroll
        for (int i = 0; i < 8; i++) acc[i] = fmaf(attS[i][cg], e, acc[i]);
    }
    #pragma unroll
    for (int i = 0; i < 8; i++)
        g_pooled[(size_t)(b0 + i) * D_ + d] = acc[i] * (1.0f / C_);
}

// ---------------- K4c: out ----------------
__global__ void __launch_bounds__(256) out_kernel(
    const float* __restrict__ out_w, const float* __restrict__ out_b,
    float* __restrict__ outp)
{
    int b0 = blockIdx.x * 8;
    int o = threadIdx.x;
    __shared__ float ps[8][D_];
    #pragma unroll
    for (int p = 0; p < 8; p++) {
        int idx = threadIdx.x + p * 256;
        ps[idx >> 8][idx & 255] = g_pooled[(size_t)b0 * D_ + idx];
    }
    __syncthreads();
    float acc[8];
    #pragma unroll
    for (int i = 0; i < 8; i++) acc[i] = 0.f;
    const float* wrow = out_w + (size_t)o * D_;
    for (int dd = 0; dd < D_; dd += 4) {
        float4 w4 = *(const float4*)(wrow + dd);
        #pragma unroll
        for (int i = 0; i < 8; i++) {
            float a = acc[i];
            a = fmaf(ps[i][dd],     w4.x, a);
            a = fmaf(ps[i][dd + 1], w4.y, a);
            a = fmaf(ps[i][dd + 2], w4.z, a);
            a = fmaf(ps[i][dd + 3], w4.w, a);
            acc[i] = a;
        }
    }
    float bias = out_b[o];
    #pragma unroll
    for (int i = 0; i < 8; i++)
        outp[(size_t)(b0 + i) * O_ + o] = acc[i] + bias;
}

extern "C" void kernel_launch(void* const* d_in, const int* in_sizes, int n_in,
                              void* d_out, int out_size)
{
    const float* hidden  = (const float*)d_in[0];
    const float* gst_emb = (const float*)d_in[1];
    const float* attn_w  = (const float*)d_in[2];
    const float* attn_b  = (const float*)d_in[3];
    const float* v       = (const float*)d_in[4];
    const float* out_w   = (const float*)d_in[5];
    const float* out_b   = (const float*)d_in[6];
    float* out  = (float*)d_out;
    float* att  = out;                   // [B, C*G]
    float* outp = out + B_ * C_ * G_;    // [B, O]

    static int smem_set = 0;
    if (!smem_set) {
        cudaFuncSetAttribute(gemm_mma_kernel,
                             cudaFuncAttributeMaxDynamicSharedMemorySize, GSMEM);
        smem_set = 1;
    }

    convert_a_kernel<<<128,  256>>>(hidden);
    convert_w_kernel<<<8192, 256>>>(attn_w);
    ebias_kernel    <<<dim3(C_, 8), 256>>>(gst_emb, attn_w, attn_b);
    gemm_mma_kernel <<<dim3(8, 2, C_), 256, GSMEM>>>();
    scores_kernel   <<<dim3(C_, 16), 256>>>(v);
    softmax_kernel  <<<B_, 512>>>(att);
    pooled_kernel   <<<B_ / 8, 256>>>(att, gst_emb);
    out_kernel      <<<B_ / 8, 256>>>(out_w, out_b, outp);
}